// round 15
// baseline (speedup 1.0000x reference)
#include <cuda_runtime.h>
#include <cuda_bf16.h>
#include <math.h>

// ============================================================================
// SphericalHarmonicsShellsConv — GB300 (sm_103a)   Round 14
//   R11 base (best 281.3us) + packed f32x2 mainloop:
//   256 thr/CTA = (channel-pair cp 0..127, row-half h 0..1), 16 slot-rows each
//   B=4, N=4096, V=2048, P=32, C=16
// Signal channel layout (concat, 256 cols):
//   l=0: [0,16) rowlen16 | l=1: [16,64) rowlen48 | l=2: [64,144) rowlen80
//   l=3: [144,256) rowlen112     (all boundaries even -> pairs never straddle)
// y rows (30): yoff={0,4,13,23}; slot(row)=row+(row>=15); slots 15,31 zero-pad
// Outputs: out[J] shape (B,V,2J+1,chJ), chJ={160,336,384,320}
// ============================================================================

#define B_ 4
#define N_ 4096
#define V_ 2048
#define P_ 32
#define BV_ (B_*V_)

#define NGROUPS 333          // 5328 output elements / 16 channels
#define MAXNNZ 64            // max CG pairs per group (<=50 incl. pad)

// pair: {coef, ybase} packed as float2 (y = bitcast int ybase, slot-mapped)
__device__ float2 g_pairs[NGROUPS * MAXNNZ];
__device__ int2   g_meta[NGROUPS];     // x = (J<<16)|local_base, y = nnz (even)
__device__ float  d_cg[27 * 343];      // dense real CG tables, stride 343/combo

// ---------------------------------------------------------------------------
// combo <-> (j,l,J) mapping
// ---------------------------------------------------------------------------
__device__ __forceinline__ void combo_decode(int combo, int& j, int& l, int& J) {
    j = -1;
    int idx = 0;
    for (int jj = 1; jj <= 3; jj++)
        for (int ll = 1; ll <= 3; ll++) {
            int lo = abs(jj - ll), hi = min(jj + ll, 3);
            for (int JJ = lo; JJ <= hi; JJ++) {
                if (idx == combo) { j = jj; l = ll; J = JJ; return; }
                idx++;
            }
        }
}

__device__ __forceinline__ int combo_index(int j, int l, int J) {
    int idx = 0;
    for (int jj = 1; jj <= 3; jj++)
        for (int ll = 1; ll <= 3; ll++) {
            int lo = abs(jj - ll), hi = min(jj + ll, 3);
            for (int JJ = lo; JJ <= hi; JJ++) {
                if (jj == j && ll == l && JJ == J) return idx;
                idx++;
            }
        }
    return -1;
}

// ---------------------------------------------------------------------------
// su2 CG in fp32 (all factorials <= 10! < 2^24, exact in fp32)
// ---------------------------------------------------------------------------
__device__ __forceinline__ float ffact(int n) {
    const float f[11] = {1.f,1.f,2.f,6.f,24.f,120.f,720.f,5040.f,40320.f,
                         362880.f,3628800.f};
    return f[n];
}

__device__ float su2_cg_f(int j1,int m1,int j2,int m2,int j3,int m3) {
    if (m3 != m1 + m2) return 0.0f;
    int vmin = max(max(-j1 + j2 + m3, -j1 + m1), 0);
    int vmax = min(min(j2 + j3 + m1, j3 - j1 + j2), j3 + m3);
    float C = sqrtf((2.f*j3 + 1.f) * ffact(j3+j1-j2) * ffact(j3-j1+j2) * ffact(j1+j2-j3)
                    * ffact(j3+m3) * ffact(j3-m3)
                    / (ffact(j1+j2+j3+1) * ffact(j1-m1) * ffact(j1+m1)
                       * ffact(j2-m2) * ffact(j2+m2)));
    float S = 0.0f;
    for (int v = vmin; v <= vmax; v++) {
        float sgn = ((v + j2 + m2) & 1) ? -1.0f : 1.0f;
        S += sgn * ffact(j2+j3+m1-v) * ffact(j1-m1+v)
             / (ffact(v) * ffact(j3-j1+j2-v) * ffact(j3+m3-v) * ffact(v+j1-j2-m3));
    }
    return C * S;
}

// Q = (-i)^l * q_real_to_complex(l); entry (r, c)
__device__ void qmat_f(int l, int r, int c, float& re, float& im) {
    const float s2 = 0.70710678118654752f;
    int m = r - l;
    float qr = 0.0f, qi = 0.0f;
    if (m < 0) {
        if (c == l - m)      qr =  s2;
        else if (c == l + m) qi = -s2;
    } else if (m == 0) {
        if (c == l) qr = 1.0f;
    } else {
        float sgn = (m & 1) ? -1.0f : 1.0f;
        if (c == l + m)      qr = sgn * s2;
        else if (c == l - m) qi = sgn * s2;
    }
    switch (l & 3) {
        case 0: re =  qr; im =  qi; break;
        case 1: re =  qi; im = -qr; break;
        case 2: re = -qr; im = -qi; break;
        default: re = -qi; im =  qr; break;
    }
}

// ---------------------------------------------------------------------------
// Init 1: fused su2 + basis change — one CTA per combo (proven: 10.3us)
// ---------------------------------------------------------------------------
__global__ void init_cg_kernel() {
    __shared__ float su2_sm[49];
    int combo = blockIdx.x;
    int e     = threadIdx.x;

    int j, l, J;
    combo_decode(combo, j, l, J);
    int dl = 2*l + 1, dJ = 2*J + 1, dj = 2*j + 1;

    if (e < 49) {
        int i = e / 7, k = e % 7;
        float v = 0.0f;
        if (i < dj && k < dl) {
            int m1 = i - j, m2 = k - l, m3 = m1 + m2;
            if (m3 >= -J && m3 <= J)
                v = su2_cg_f(j, m1, l, m2, J, m3);
        }
        su2_sm[e] = v;
    }
    __syncthreads();

    if (e >= 343) return;
    int tot = dj * dl * dJ;
    if (e >= tot) { d_cg[combo * 343 + e] = 0.0f; return; }

    int pp  = e % dJ;
    int rem = e / dJ;
    int b   = rem % dl;
    int a   = rem / dl;

    float accR = 0.0f;
    for (int i = 0; i < dj; i++) {
        float q1r, q1i; qmat_f(j, i, a, q1r, q1i);
        if (q1r == 0.0f && q1i == 0.0f) continue;
        int m1 = i - j;
        for (int k = 0; k < dl; k++) {
            int m2 = k - l, m3 = m1 + m2;
            if (m3 < -J || m3 > J) continue;
            float q2r, q2i; qmat_f(l, k, b, q2r, q2i);
            if (q2r == 0.0f && q2i == 0.0f) continue;
            float s = su2_sm[i * 7 + k];
            if (s == 0.0f) continue;
            float q3r, q3i; qmat_f(J, J + m3, pp, q3r, q3i);
            q3i = -q3i;   // conj
            float tr = q1r*q2r - q1i*q2i, ti = q1r*q2i + q1i*q2r;
            accR += (tr*q3r - ti*q3i) * s;
        }
    }
    d_cg[combo * 343 + e] = accR;
}

// ---------------------------------------------------------------------------
// Init 2: build the 333-group sparse program (nnz padded to even)
//   ybase = slot(row)*256 + column offset, slot(row)=row+(row>=15)
// ---------------------------------------------------------------------------
struct Seg { signed char type, j, l; short cstart; };  // 0=D0(l=0),1=D1(j=0),2=CG,-1=end

__device__ __forceinline__ int yslot(int row) { return row + (row >= 15 ? 1 : 0); }

__global__ void init_prog_kernel() {
    int g = blockIdx.x * blockDim.x + threadIdx.x;
    if (g >= NGROUPS) return;

    const int gcum[5]    = {0, 10, 73, 193, 333};
    const int gperrow[4] = {10, 21, 24, 20};
    const int chJ[4]     = {160, 336, 384, 320};
    const int yoff[4]    = {0, 4, 13, 23};
    const int coff[4]    = {0, 16, 64, 144};

    const Seg segJ0[] = {{0,0,0,0},{2,1,1,64},{2,2,2,112},{2,3,3,144},{-1,0,0,160}};
    const Seg segJ1[] = {{0,1,0,0},{1,0,1,48},{2,1,1,112},{2,2,1,160},{2,1,2,192},
                         {2,2,2,240},{2,3,2,272},{2,2,3,288},{2,3,3,320},{-1,0,0,336}};
    const Seg segJ2[] = {{0,2,0,0},{1,0,2,32},{2,1,1,96},{2,2,1,144},{2,3,1,176},
                         {2,1,2,192},{2,2,2,240},{2,3,2,272},{2,1,3,288},{2,2,3,336},
                         {2,3,3,368},{-1,0,0,384}};
    const Seg segJ3[] = {{0,3,0,0},{1,0,3,16},{2,2,1,80},{2,3,1,112},{2,1,2,128},
                         {2,2,2,176},{2,3,2,208},{2,1,3,224},{2,2,3,272},{2,3,3,304},
                         {-1,0,0,320}};
    const Seg* segs[4] = {segJ0, segJ1, segJ2, segJ3};

    int J  = (g < 10) ? 0 : (g < 73) ? 1 : (g < 193) ? 2 : 3;
    int rl = g - gcum[J];
    int p  = rl / gperrow[J];
    int c  = (rl % gperrow[J]) * 16;

    const Seg* st = segs[J];
    int si = 0;
    while (st[si + 1].type != -1 && st[si + 1].cstart <= c) si++;
    Seg sg = st[si];
    int cl = c - sg.cstart;
    int i  = cl >> 4;

    float2* out = &g_pairs[g * MAXNNZ];
    int n = 0;
    if (sg.type == 0) {              // l=0 direct, j=J
        out[n].x = 1.0f;
        out[n].y = __int_as_float(yslot(yoff[J] + p * (4 - J) + i) * 256);
        n++;
    } else if (sg.type == 1) {       // j=0 direct, l=J
        out[n].x = 1.0f;
        out[n].y = __int_as_float(yslot(i) * 256 + coff[J] + p * 16);
        n++;
    } else {                         // CG contraction
        int j = sg.j, l = sg.l;
        int cb = combo_index(j, l, J) * 343;
        int dl = 2*l + 1, dJ = 2*J + 1;
        for (int nn = 0; nn < 2*j + 1; nn++)
            for (int m = 0; m < dl; m++) {
                float coef = d_cg[cb + (nn * dl + m) * dJ + p];
                if (fabsf(coef) > 1e-6f) {
                    out[n].x = coef;
                    out[n].y = __int_as_float(yslot(yoff[j] + nn * (4 - j) + i) * 256
                                              + coff[l] + m * 16);
                    n++;
                }
            }
    }
    if (n & 1) {                     // pad to even for float4 streaming
        out[n].x = 0.0f;
        out[n].y = __int_as_float(0);
        n++;
    }
    g_meta[g] = make_int2((J << 16) | (p * chJ[J] + c), n);
}

// ---------------------------------------------------------------------------
// Main kernel: one CTA (256 threads) per (b,v)
//   thread = (channel-pair cp = tid&127, half h = tid>>7); 16 slot-rows each
//   packed fma.rn.f32x2: 16 FFMA2 per p instead of 30 scalar FFMA
// ---------------------------------------------------------------------------
__device__ __forceinline__ void ffma2(unsigned long long& d,
                                      unsigned long long a,
                                      unsigned long long b) {
    asm("fma.rn.f32x2 %0, %1, %2, %3;" : "=l"(d) : "l"(a), "l"(b), "l"(d));
}

__global__ __launch_bounds__(256, 3)
void conv_kernel(const float* __restrict__ x0, const float* __restrict__ x1,
                 const float* __restrict__ x2, const float* __restrict__ x3,
                 const int*   __restrict__ patches,
                 const float* __restrict__ kernels,
                 float* __restrict__ out)
{
    __shared__ __align__(16) unsigned long long Ksm2[32][32]; // {k,k} per slot; 15/31=0
    __shared__ int rowOff[32];
    __shared__ __align__(16) float ysm[32 * 256];             // y[slot][ch]

    const int bv  = blockIdx.x;
    const int tid = threadIdx.x;
    const int cp  = tid & 127;     // channel pair: channels 2cp, 2cp+1
    const int h   = tid >> 7;      // row half: slots h*16 .. h*16+15

    // stage K (32x30) into padded slots, duplicated into both 32-bit halves
    const float* kp = kernels + (size_t)bv * (P_ * 30);
    for (int t = tid; t < P_ * 32; t += 256) {
        int pr = t >> 5, slot = t & 31;
        float v = 0.0f;
        if (slot != 15 && slot != 31) {
            int y = (slot < 15) ? slot : slot - 1;
            v = kp[pr * 30 + y];
        }
        unsigned int ui = __float_as_uint(v);
        Ksm2[pr][slot] = ((unsigned long long)ui << 32) | ui;
    }
    if (tid < P_) {
        int2 pi = ((const int2*)patches)[(size_t)bv * P_ + tid];
        rowOff[tid] = pi.x * N_ + pi.y;           // row index (fits int)
    }

    // channel-pair -> source decode (pair never straddles tensor boundaries)
    const int c = 2 * cp;
    const float* xb; int rowlen, cloc;
    if (c < 16)       { xb = x0; rowlen = 16;  cloc = c;       }
    else if (c < 64)  { xb = x1; rowlen = 48;  cloc = c - 16;  }
    else if (c < 144) { xb = x2; rowlen = 80;  cloc = c - 64;  }
    else              { xb = x3; rowlen = 112; cloc = c - 144; }

    __syncthreads();

    // y[slot=h*16+i, {c,c+1}] = sum_p K[p][slot] * g[p,{c,c+1}]
    unsigned long long acc[16];
    #pragma unroll
    for (int y = 0; y < 16; y++) acc[y] = 0ULL;

    #pragma unroll 8
    for (int p = 0; p < P_; p++) {
        unsigned long long gv =
            __ldg((const unsigned long long*)(xb + (unsigned)(rowOff[p] * rowlen + cloc)));
        const ulonglong2* krow = (const ulonglong2*)&Ksm2[p][h * 16];
        ulonglong2 k0 = krow[0], k1 = krow[1], k2 = krow[2], k3 = krow[3];
        ulonglong2 k4 = krow[4], k5 = krow[5], k6 = krow[6], k7 = krow[7];
        ffma2(acc[ 0], k0.x, gv);
        ffma2(acc[ 1], k0.y, gv);
        ffma2(acc[ 2], k1.x, gv);
        ffma2(acc[ 3], k1.y, gv);
        ffma2(acc[ 4], k2.x, gv);
        ffma2(acc[ 5], k2.y, gv);
        ffma2(acc[ 6], k3.x, gv);
        ffma2(acc[ 7], k3.y, gv);
        ffma2(acc[ 8], k4.x, gv);
        ffma2(acc[ 9], k4.y, gv);
        ffma2(acc[10], k5.x, gv);
        ffma2(acc[11], k5.y, gv);
        ffma2(acc[12], k6.x, gv);
        ffma2(acc[13], k6.y, gv);
        ffma2(acc[14], k7.x, gv);
        ffma2(acc[15], k7.y, gv);
    }

    #pragma unroll
    for (int y = 0; y < 16; y++)
        *(unsigned long long*)&ysm[(h * 16 + y) * 256 + c] = acc[y];
    __syncthreads();

    // epilogue (R7-proven): 333 groups x 4 quarters; 2 pairs per 16B load
    const size_t outBase[4] = {0, 1310720, 9568256, 25296896};
    const int    slab[4]    = {160, 1008, 1920, 2240};

    for (int item = tid; item < NGROUPS * 4; item += 256) {
        int g = item >> 2, q = item & 3;
        int2 gm = g_meta[g];
        int nnz = gm.y;                            // even
        const float4* pr4 = (const float4*)&g_pairs[g * MAXNNZ];
        const float* ybase = ysm + q * 4;
        float4 a = make_float4(0.f, 0.f, 0.f, 0.f);
        #pragma unroll 2
        for (int k = 0; k < nnz; k += 2) {
            float4 rec = pr4[k >> 1];              // {c0, yb0, c1, yb1}
            const float4 v0 = *(const float4*)&ybase[__float_as_int(rec.y)];
            const float4 v1 = *(const float4*)&ybase[__float_as_int(rec.w)];
            a.x = fmaf(rec.x, v0.x, a.x);
            a.y = fmaf(rec.x, v0.y, a.y);
            a.z = fmaf(rec.x, v0.z, a.z);
            a.w = fmaf(rec.x, v0.w, a.w);
            a.x = fmaf(rec.z, v1.x, a.x);
            a.y = fmaf(rec.z, v1.y, a.y);
            a.z = fmaf(rec.z, v1.z, a.z);
            a.w = fmaf(rec.z, v1.w, a.w);
        }
        int J = gm.x >> 16;
        int local = gm.x & 0xffff;
        size_t off = outBase[J] + (size_t)bv * slab[J] + local + q * 4;
        *(float4*)&out[off] = a;
    }
}

// ---------------------------------------------------------------------------
extern "C" void kernel_launch(void* const* d_in, const int* in_sizes, int n_in,
                              void* d_out, int out_size) {
    const float* x0      = (const float*)d_in[0];
    const float* x1      = (const float*)d_in[1];
    const float* x2      = (const float*)d_in[2];
    const float* x3      = (const float*)d_in[3];
    const int*   patches = (const int*)d_in[4];
    const float* kernels = (const float*)d_in[5];
    float*       out     = (float*)d_out;

    init_cg_kernel<<<27, 352>>>();
    init_prog_kernel<<<3, 128>>>();
    conv_kernel<<<BV_, 256>>>(x0, x1, x2, x3, patches, kernels, out);
}

// round 16
// speedup vs baseline: 1.1831x; 1.1831x over previous
#include <cuda_runtime.h>
#include <cuda_bf16.h>
#include <math.h>

// ============================================================================
// SphericalHarmonicsShellsConv — GB300 (sm_103a)   Round 15
//   R11 dataflow (best 281.3us) + occupancy 4 CTAs/SM (regs<=64 via chunked K)
//   B=4, N=4096, V=2048, P=32, C=16
// Signal channel layout (concat, 256 cols):
//   l=0: [0,16) rowlen16 | l=1: [16,64) rowlen48 | l=2: [64,144) rowlen80
//   l=3: [144,256) rowlen112
// y rows (30): yoff={0,4,13,23}; row = yoff[j] + n*(4-j) + i
// Outputs: out[J] shape (B,V,2J+1,chJ), chJ={160,336,384,320}
// ============================================================================

#define B_ 4
#define N_ 4096
#define V_ 2048
#define P_ 32
#define BV_ (B_*V_)

#define NGROUPS 333          // 5328 output elements / 16 channels
#define MAXNNZ 64            // max CG pairs per group (<=50 incl. pad)

// pair: {coef, ybase} packed as float2 (y = bitcast int ybase)
__device__ float2 g_pairs[NGROUPS * MAXNNZ];
__device__ int2   g_meta[NGROUPS];     // x = (J<<16)|local_base, y = nnz (even)
__device__ float  d_cg[27 * 343];      // dense real CG tables, stride 343/combo

// ---------------------------------------------------------------------------
// combo <-> (j,l,J) mapping
// ---------------------------------------------------------------------------
__device__ __forceinline__ void combo_decode(int combo, int& j, int& l, int& J) {
    j = -1;
    int idx = 0;
    for (int jj = 1; jj <= 3; jj++)
        for (int ll = 1; ll <= 3; ll++) {
            int lo = abs(jj - ll), hi = min(jj + ll, 3);
            for (int JJ = lo; JJ <= hi; JJ++) {
                if (idx == combo) { j = jj; l = ll; J = JJ; return; }
                idx++;
            }
        }
}

__device__ __forceinline__ int combo_index(int j, int l, int J) {
    int idx = 0;
    for (int jj = 1; jj <= 3; jj++)
        for (int ll = 1; ll <= 3; ll++) {
            int lo = abs(jj - ll), hi = min(jj + ll, 3);
            for (int JJ = lo; JJ <= hi; JJ++) {
                if (jj == j && ll == l && JJ == J) return idx;
                idx++;
            }
        }
    return -1;
}

// ---------------------------------------------------------------------------
// su2 CG in fp32 (all factorials <= 10! < 2^24, exact in fp32)
// ---------------------------------------------------------------------------
__device__ __forceinline__ float ffact(int n) {
    const float f[11] = {1.f,1.f,2.f,6.f,24.f,120.f,720.f,5040.f,40320.f,
                         362880.f,3628800.f};
    return f[n];
}

__device__ float su2_cg_f(int j1,int m1,int j2,int m2,int j3,int m3) {
    if (m3 != m1 + m2) return 0.0f;
    int vmin = max(max(-j1 + j2 + m3, -j1 + m1), 0);
    int vmax = min(min(j2 + j3 + m1, j3 - j1 + j2), j3 + m3);
    float C = sqrtf((2.f*j3 + 1.f) * ffact(j3+j1-j2) * ffact(j3-j1+j2) * ffact(j1+j2-j3)
                    * ffact(j3+m3) * ffact(j3-m3)
                    / (ffact(j1+j2+j3+1) * ffact(j1-m1) * ffact(j1+m1)
                       * ffact(j2-m2) * ffact(j2+m2)));
    float S = 0.0f;
    for (int v = vmin; v <= vmax; v++) {
        float sgn = ((v + j2 + m2) & 1) ? -1.0f : 1.0f;
        S += sgn * ffact(j2+j3+m1-v) * ffact(j1-m1+v)
             / (ffact(v) * ffact(j3-j1+j2-v) * ffact(j3+m3-v) * ffact(v+j1-j2-m3));
    }
    return C * S;
}

// Q = (-i)^l * q_real_to_complex(l); entry (r, c)
__device__ void qmat_f(int l, int r, int c, float& re, float& im) {
    const float s2 = 0.70710678118654752f;
    int m = r - l;
    float qr = 0.0f, qi = 0.0f;
    if (m < 0) {
        if (c == l - m)      qr =  s2;
        else if (c == l + m) qi = -s2;
    } else if (m == 0) {
        if (c == l) qr = 1.0f;
    } else {
        float sgn = (m & 1) ? -1.0f : 1.0f;
        if (c == l + m)      qr = sgn * s2;
        else if (c == l - m) qi = sgn * s2;
    }
    switch (l & 3) {
        case 0: re =  qr; im =  qi; break;
        case 1: re =  qi; im = -qr; break;
        case 2: re = -qr; im = -qi; break;
        default: re = -qi; im =  qr; break;
    }
}

// ---------------------------------------------------------------------------
// Init 1: fused su2 + basis change — one CTA per combo (proven: 10.3us)
// ---------------------------------------------------------------------------
__global__ void init_cg_kernel() {
    __shared__ float su2_sm[49];
    int combo = blockIdx.x;
    int e     = threadIdx.x;

    int j, l, J;
    combo_decode(combo, j, l, J);
    int dl = 2*l + 1, dJ = 2*J + 1, dj = 2*j + 1;

    if (e < 49) {
        int i = e / 7, k = e % 7;
        float v = 0.0f;
        if (i < dj && k < dl) {
            int m1 = i - j, m2 = k - l, m3 = m1 + m2;
            if (m3 >= -J && m3 <= J)
                v = su2_cg_f(j, m1, l, m2, J, m3);
        }
        su2_sm[e] = v;
    }
    __syncthreads();

    if (e >= 343) return;
    int tot = dj * dl * dJ;
    if (e >= tot) { d_cg[combo * 343 + e] = 0.0f; return; }

    int pp  = e % dJ;
    int rem = e / dJ;
    int b   = rem % dl;
    int a   = rem / dl;

    float accR = 0.0f;
    for (int i = 0; i < dj; i++) {
        float q1r, q1i; qmat_f(j, i, a, q1r, q1i);
        if (q1r == 0.0f && q1i == 0.0f) continue;
        int m1 = i - j;
        for (int k = 0; k < dl; k++) {
            int m2 = k - l, m3 = m1 + m2;
            if (m3 < -J || m3 > J) continue;
            float q2r, q2i; qmat_f(l, k, b, q2r, q2i);
            if (q2r == 0.0f && q2i == 0.0f) continue;
            float s = su2_sm[i * 7 + k];
            if (s == 0.0f) continue;
            float q3r, q3i; qmat_f(J, J + m3, pp, q3r, q3i);
            q3i = -q3i;   // conj
            float tr = q1r*q2r - q1i*q2i, ti = q1r*q2i + q1i*q2r;
            accR += (tr*q3r - ti*q3i) * s;
        }
    }
    d_cg[combo * 343 + e] = accR;
}

// ---------------------------------------------------------------------------
// Init 2: build the 333-group sparse program (nnz padded to even)
// ---------------------------------------------------------------------------
struct Seg { signed char type, j, l; short cstart; };  // 0=D0(l=0),1=D1(j=0),2=CG,-1=end

__global__ void init_prog_kernel() {
    int g = blockIdx.x * blockDim.x + threadIdx.x;
    if (g >= NGROUPS) return;

    const int gcum[5]    = {0, 10, 73, 193, 333};
    const int gperrow[4] = {10, 21, 24, 20};
    const int chJ[4]     = {160, 336, 384, 320};
    const int yoff[4]    = {0, 4, 13, 23};
    const int coff[4]    = {0, 16, 64, 144};

    const Seg segJ0[] = {{0,0,0,0},{2,1,1,64},{2,2,2,112},{2,3,3,144},{-1,0,0,160}};
    const Seg segJ1[] = {{0,1,0,0},{1,0,1,48},{2,1,1,112},{2,2,1,160},{2,1,2,192},
                         {2,2,2,240},{2,3,2,272},{2,2,3,288},{2,3,3,320},{-1,0,0,336}};
    const Seg segJ2[] = {{0,2,0,0},{1,0,2,32},{2,1,1,96},{2,2,1,144},{2,3,1,176},
                         {2,1,2,192},{2,2,2,240},{2,3,2,272},{2,1,3,288},{2,2,3,336},
                         {2,3,3,368},{-1,0,0,384}};
    const Seg segJ3[] = {{0,3,0,0},{1,0,3,16},{2,2,1,80},{2,3,1,112},{2,1,2,128},
                         {2,2,2,176},{2,3,2,208},{2,1,3,224},{2,2,3,272},{2,3,3,304},
                         {-1,0,0,320}};
    const Seg* segs[4] = {segJ0, segJ1, segJ2, segJ3};

    int J  = (g < 10) ? 0 : (g < 73) ? 1 : (g < 193) ? 2 : 3;
    int rl = g - gcum[J];
    int p  = rl / gperrow[J];
    int c  = (rl % gperrow[J]) * 16;

    const Seg* st = segs[J];
    int si = 0;
    while (st[si + 1].type != -1 && st[si + 1].cstart <= c) si++;
    Seg sg = st[si];
    int cl = c - sg.cstart;
    int i  = cl >> 4;

    float2* out = &g_pairs[g * MAXNNZ];
    int n = 0;
    if (sg.type == 0) {              // l=0 direct, j=J
        out[n].x = 1.0f;
        out[n].y = __int_as_float((yoff[J] + p * (4 - J) + i) * 256);
        n++;
    } else if (sg.type == 1) {       // j=0 direct, l=J
        out[n].x = 1.0f;
        out[n].y = __int_as_float(i * 256 + coff[J] + p * 16);
        n++;
    } else {                         // CG contraction
        int j = sg.j, l = sg.l;
        int cb = combo_index(j, l, J) * 343;
        int dl = 2*l + 1, dJ = 2*J + 1;
        for (int nn = 0; nn < 2*j + 1; nn++)
            for (int m = 0; m < dl; m++) {
                float coef = d_cg[cb + (nn * dl + m) * dJ + p];
                if (fabsf(coef) > 1e-6f) {
                    out[n].x = coef;
                    out[n].y = __int_as_float((yoff[j] + nn * (4 - j) + i) * 256
                                              + coff[l] + m * 16);
                    n++;
                }
            }
    }
    if (n & 1) {                     // pad to even for float4 streaming
        out[n].x = 0.0f;
        out[n].y = __int_as_float(0);
        n++;
    }
    g_meta[g] = make_int2((J << 16) | (p * chJ[J] + c), n);
}

// ---------------------------------------------------------------------------
// Main kernel: one CTA (256 threads) per (b,v); 4 CTAs/SM; chunked K loads
// ---------------------------------------------------------------------------
__global__ __launch_bounds__(256, 4)
void conv_kernel(const float* __restrict__ x0, const float* __restrict__ x1,
                 const float* __restrict__ x2, const float* __restrict__ x3,
                 const int*   __restrict__ patches,
                 const float* __restrict__ kernels,
                 float* __restrict__ out)
{
    __shared__ __align__(16) float Ksm[32][32];   // K[p][y], rows 16B-aligned
    __shared__ int   rowOff[32];
    __shared__ __align__(16) float ysm[30 * 256];

    const int bv  = blockIdx.x;
    const int tid = threadIdx.x;

    // stage K (32x30) and patch row indices; zero the 2-entry row tail
    const float* kp = kernels + (size_t)bv * (P_ * 30);
    for (int t = tid; t < P_ * 32; t += 256) {
        int pr = t >> 5, yy = t & 31;
        Ksm[pr][yy] = (yy < 30) ? kp[pr * 30 + yy] : 0.0f;
    }
    if (tid < P_) {
        int2 pi = ((const int2*)patches)[(size_t)bv * P_ + tid];
        rowOff[tid] = pi.x * N_ + pi.y;           // row index (fits int)
    }

    // column -> source decode (thread owns channel column tid)
    const float* xb; int rowlen, cloc;
    if (tid < 16)       { xb = x0; rowlen = 16;  cloc = tid;       }
    else if (tid < 64)  { xb = x1; rowlen = 48;  cloc = tid - 16;  }
    else if (tid < 144) { xb = x2; rowlen = 80;  cloc = tid - 64;  }
    else                { xb = x3; rowlen = 112; cloc = tid - 144; }

    __syncthreads();

    // y[yrow, c=tid] = sum_p K[p,yrow] * g[p,c]
    float acc[30];
    #pragma unroll
    for (int y = 0; y < 30; y++) acc[y] = 0.0f;

    #pragma unroll 4
    for (int p = 0; p < P_; p++) {
        float gv = __ldg(xb + (unsigned)(rowOff[p] * rowlen + cloc));
        const float4* krow = (const float4*)Ksm[p];
        // chunk A: rows 0-15 (4 float4 live)
        {
            float4 k0 = krow[0], k1 = krow[1], k2 = krow[2], k3 = krow[3];
            acc[ 0] = fmaf(k0.x, gv, acc[ 0]);
            acc[ 1] = fmaf(k0.y, gv, acc[ 1]);
            acc[ 2] = fmaf(k0.z, gv, acc[ 2]);
            acc[ 3] = fmaf(k0.w, gv, acc[ 3]);
            acc[ 4] = fmaf(k1.x, gv, acc[ 4]);
            acc[ 5] = fmaf(k1.y, gv, acc[ 5]);
            acc[ 6] = fmaf(k1.z, gv, acc[ 6]);
            acc[ 7] = fmaf(k1.w, gv, acc[ 7]);
            acc[ 8] = fmaf(k2.x, gv, acc[ 8]);
            acc[ 9] = fmaf(k2.y, gv, acc[ 9]);
            acc[10] = fmaf(k2.z, gv, acc[10]);
            acc[11] = fmaf(k2.w, gv, acc[11]);
            acc[12] = fmaf(k3.x, gv, acc[12]);
            acc[13] = fmaf(k3.y, gv, acc[13]);
            acc[14] = fmaf(k3.z, gv, acc[14]);
            acc[15] = fmaf(k3.w, gv, acc[15]);
        }
        // chunk B: rows 16-29 (4 float4 live)
        {
            float4 k4 = krow[4], k5 = krow[5], k6 = krow[6], k7 = krow[7];
            acc[16] = fmaf(k4.x, gv, acc[16]);
            acc[17] = fmaf(k4.y, gv, acc[17]);
            acc[18] = fmaf(k4.z, gv, acc[18]);
            acc[19] = fmaf(k4.w, gv, acc[19]);
            acc[20] = fmaf(k5.x, gv, acc[20]);
            acc[21] = fmaf(k5.y, gv, acc[21]);
            acc[22] = fmaf(k5.z, gv, acc[22]);
            acc[23] = fmaf(k5.w, gv, acc[23]);
            acc[24] = fmaf(k6.x, gv, acc[24]);
            acc[25] = fmaf(k6.y, gv, acc[25]);
            acc[26] = fmaf(k6.z, gv, acc[26]);
            acc[27] = fmaf(k6.w, gv, acc[27]);
            acc[28] = fmaf(k7.x, gv, acc[28]);
            acc[29] = fmaf(k7.y, gv, acc[29]);
        }
    }

    #pragma unroll
    for (int y = 0; y < 30; y++) ysm[y * 256 + tid] = acc[y];
    __syncthreads();

    // epilogue (R7-proven): 333 groups x 4 quarters; 2 pairs per 16B load
    const size_t outBase[4] = {0, 1310720, 9568256, 25296896};
    const int    slab[4]    = {160, 1008, 1920, 2240};

    for (int item = tid; item < NGROUPS * 4; item += 256) {
        int g = item >> 2, q = item & 3;
        int2 gm = g_meta[g];
        int nnz = gm.y;                            // even
        const float4* pr4 = (const float4*)&g_pairs[g * MAXNNZ];
        const float* ybase = ysm + q * 4;
        float4 a = make_float4(0.f, 0.f, 0.f, 0.f);
        #pragma unroll 2
        for (int k = 0; k < nnz; k += 2) {
            float4 rec = pr4[k >> 1];              // {c0, yb0, c1, yb1}
            const float4 v0 = *(const float4*)&ybase[__float_as_int(rec.y)];
            const float4 v1 = *(const float4*)&ybase[__float_as_int(rec.w)];
            a.x = fmaf(rec.x, v0.x, a.x);
            a.y = fmaf(rec.x, v0.y, a.y);
            a.z = fmaf(rec.x, v0.z, a.z);
            a.w = fmaf(rec.x, v0.w, a.w);
            a.x = fmaf(rec.z, v1.x, a.x);
            a.y = fmaf(rec.z, v1.y, a.y);
            a.z = fmaf(rec.z, v1.z, a.z);
            a.w = fmaf(rec.z, v1.w, a.w);
        }
        int J = gm.x >> 16;
        int local = gm.x & 0xffff;
        size_t off = outBase[J] + (size_t)bv * slab[J] + local + q * 4;
        *(float4*)&out[off] = a;
    }
}

// ---------------------------------------------------------------------------
extern "C" void kernel_launch(void* const* d_in, const int* in_sizes, int n_in,
                              void* d_out, int out_size) {
    const float* x0      = (const float*)d_in[0];
    const float* x1      = (const float*)d_in[1];
    const float* x2      = (const float*)d_in[2];
    const float* x3      = (const float*)d_in[3];
    const int*   patches = (const int*)d_in[4];
    const float* kernels = (const float*)d_in[5];
    float*       out     = (float*)d_out;

    init_cg_kernel<<<27, 352>>>();
    init_prog_kernel<<<3, 128>>>();
    conv_kernel<<<BV_, 256>>>(x0, x1, x2, x3, patches, kernels, out);
}